// round 13
// baseline (speedup 1.0000x reference)
#include <cuda_runtime.h>
#include <cuda_fp16.h>
#include <cstdint>

#define N_NODES 50000
#define N_EDGES 800000
#define D 128
#define R 4
#define NSEG (N_NODES * R)      // 200000
#define NLAYER 3
#define KTOT 640                // R*D + D
#define MPAD 50048              // 391 * 128
#define NTILES 391
#define NCHUNK 10               // K chunks of 64 fp16 (128B rows)

// ---------------- static device scratch ----------------
__device__ __align__(16) __half g_ah[(size_t)MPAD * KTOT];        // A fp16 [node][640]
__device__ __align__(16) __half g_bh[(size_t)NLAYER * D * KTOT];  // B fp16 [l][n][k]
__device__ float g_x1[(size_t)N_NODES * D];
__device__ float g_x2[(size_t)N_NODES * D];
__device__ int   g_cnt[NSEG];
__device__ int   g_off[NSEG + 1];
__device__ int   g_cursor[NSEG];
__device__ int   g_bsum[256];
__device__ int   g_srcs[N_EDGES];

// ---------------- helpers ----------------
__device__ __forceinline__ uint32_t smem_to_u32(const void* p) {
    uint32_t a;
    asm("{ .reg .u64 t; cvta.to.shared.u64 t, %1; cvt.u32.u64 %0, t; }"
        : "=r"(a) : "l"(p));
    return a;
}

#define CP16(sm, gp) \
    asm volatile("cp.async.cg.shared.global [%0], [%1], 16;" :: "r"(sm), "l"(gp))

__device__ __forceinline__ void ldsm_x4(uint32_t* f, uint32_t addr) {
    asm volatile("ldmatrix.sync.aligned.m8n8.x4.shared.b16 {%0,%1,%2,%3}, [%4];"
                 : "=r"(f[0]), "=r"(f[1]), "=r"(f[2]), "=r"(f[3]) : "r"(addr));
}

__device__ __forceinline__ void mma16816(float* d, const uint32_t* a,
                                         uint32_t b0, uint32_t b1) {
    asm volatile(
        "mma.sync.aligned.m16n8k16.row.col.f32.f16.f16.f32 "
        "{%0,%1,%2,%3}, {%4,%5,%6,%7}, {%8,%9}, {%0,%1,%2,%3};"
        : "+f"(d[0]), "+f"(d[1]), "+f"(d[2]), "+f"(d[3])
        : "r"(a[0]), "r"(a[1]), "r"(a[2]), "r"(a[3]), "r"(b0), "r"(b1));
}

// ---------------- CSR build ----------------
__global__ void k_zero_cnt() {
    int i = blockIdx.x * blockDim.x + threadIdx.x;
    if (i < NSEG) g_cnt[i] = 0;
}

__global__ void k_hist(const int* __restrict__ dst, const int* __restrict__ et) {
    int e = blockIdx.x * blockDim.x + threadIdx.x;
    if (e < N_EDGES) atomicAdd(&g_cnt[dst[e] * R + et[e]], 1);
}

__global__ void k_scan1() {
    __shared__ int sh[1024];
    int t = threadIdx.x;
    int i = blockIdx.x * 1024 + t;
    int v = (i < NSEG) ? g_cnt[i] : 0;
    sh[t] = v;
    __syncthreads();
    for (int d = 1; d < 1024; d <<= 1) {
        int add = (t >= d) ? sh[t - d] : 0;
        __syncthreads();
        sh[t] += add;
        __syncthreads();
    }
    if (i < NSEG) g_off[i] = sh[t] - v;
    if (t == 1023) g_bsum[blockIdx.x] = sh[1023];
}

// fused scan2+scan3: every block redundantly scans the block sums
__global__ void k_scan23(int nb) {
    __shared__ int sh[256];
    int t = threadIdx.x;
    if (t < 256) sh[t] = (t < nb) ? g_bsum[t] : 0;
    __syncthreads();
    for (int d = 1; d < 256; d <<= 1) {
        int add = 0;
        if (t < 256 && t >= d) add = sh[t - d];
        __syncthreads();
        if (t < 256) sh[t] += add;
        __syncthreads();
    }
    int boff = (blockIdx.x > 0) ? sh[blockIdx.x - 1] : 0;
    int i = blockIdx.x * 1024 + t;
    if (i < NSEG) {
        int o = g_off[i] + boff;
        g_off[i] = o;
        g_cursor[i] = o;
    }
    if (i == 0) g_off[NSEG] = N_EDGES;
}

__global__ void k_scatter(const int* __restrict__ src, const int* __restrict__ dst,
                          const int* __restrict__ et) {
    int e = blockIdx.x * blockDim.x + threadIdx.x;
    if (e < N_EDGES) {
        int seg = dst[e] * R + et[e];
        int pos = atomicAdd(&g_cursor[seg], 1);
        g_srcs[pos] = src[e];
    }
}

// ---------------- weight prep: transpose + fp16 ----------------
__global__ void k_bprep(const float* __restrict__ W, const float* __restrict__ root) {
    int i = blockIdx.x * 256 + threadIdx.x;     // over NLAYER*D*KTOT
    if (i >= NLAYER * D * KTOT) return;
    int k = i % KTOT;
    int t = i / KTOT;
    int n = t % D;
    int l = t / D;
    float w;
    if (k < 512) {
        int r = k >> 7, din = k & 127;
        w = W[(((size_t)l * R + r) * D + din) * D + n];
    } else {
        w = root[((size_t)l * D + (k - 512)) * D + n];
    }
    g_bh[i] = __float2half_rn(w);
}

// ---------------- fill self-columns (512..639) of A from fp32 activations ----------------
__global__ void k_convx(const float* __restrict__ x) {
    int row = blockIdx.x * 8 + (threadIdx.x >> 5);
    if (row >= N_NODES) return;
    int lane = threadIdx.x & 31;
    float4 v = *reinterpret_cast<const float4*>(x + (size_t)row * D + lane * 4);
    __half h[4];
    h[0] = __float2half_rn(v.x);
    h[1] = __float2half_rn(v.y);
    h[2] = __float2half_rn(v.z);
    h[3] = __float2half_rn(v.w);
    size_t o = (size_t)row * KTOT + 512 + lane * 4;
    *reinterpret_cast<uint2*>(&g_ah[o]) = *reinterpret_cast<uint2*>(h);
}

// ---------------- segment-mean aggregation (warp per segment, MLP-4 gathers) ----------------
__global__ void k_agg() {
    int seg = blockIdx.x * 8 + (threadIdx.x >> 5);
    if (seg >= NSEG) return;
    int lane = threadIdx.x & 31;
    int beg = g_off[seg];
    int end = g_off[seg + 1];
    float ax = 0.f, ay = 0.f, az = 0.f, aw = 0.f;

    auto addv = [&](uint2 raw) {
        __half2 h01 = *reinterpret_cast<__half2*>(&raw.x);
        __half2 h23 = *reinterpret_cast<__half2*>(&raw.y);
        float2 f01 = __half22float2(h01);
        float2 f23 = __half22float2(h23);
        ax += f01.x; ay += f01.y; az += f23.x; aw += f23.y;
    };
    auto gaddr = [&](int s) {
        return reinterpret_cast<const uint2*>(&g_ah[(size_t)s * KTOT + 512 + lane * 4]);
    };

    for (int jb = beg; jb < end; jb += 32) {
        int j = jb + lane;
        // one coalesced batch load of up to 32 src ids — kills the per-edge
        // srcs->gather dependency chain
        int sn = (j < end) ? g_srcs[j] : 0;
        int cnt = min(end - jb, 32);
        int i = 0;
        for (; i + 4 <= cnt; i += 4) {
            int s0 = __shfl_sync(0xFFFFFFFFu, sn, i);
            int s1 = __shfl_sync(0xFFFFFFFFu, sn, i + 1);
            int s2 = __shfl_sync(0xFFFFFFFFu, sn, i + 2);
            int s3 = __shfl_sync(0xFFFFFFFFu, sn, i + 3);
            uint2 r0 = *gaddr(s0);   // 4 independent gathers in flight (MLP 4)
            uint2 r1 = *gaddr(s1);
            uint2 r2 = *gaddr(s2);
            uint2 r3 = *gaddr(s3);
            addv(r0); addv(r1); addv(r2); addv(r3);
        }
        for (; i < cnt; i++) {
            int s = __shfl_sync(0xFFFFFFFFu, sn, i);
            addv(*gaddr(s));
        }
    }

    float inv = (end > beg) ? 1.0f / (float)(end - beg) : 0.0f;
    __half h[4];
    h[0] = __float2half_rn(ax * inv);
    h[1] = __float2half_rn(ay * inv);
    h[2] = __float2half_rn(az * inv);
    h[3] = __float2half_rn(aw * inv);
    int node = seg >> 2;
    int r = seg & 3;
    size_t o = (size_t)node * KTOT + r * 128 + lane * 4;
    *reinterpret_cast<uint2*>(&g_ah[o]) = *reinterpret_cast<uint2*>(h);
}

// ---------------- HMMA GEMM + fused relu/residual/LayerNorm, occupancy-2 ----------------
// smem: [0:512) bias, [512:1024) gamma, [1024:1536) beta
//       A tiles (double buffered): 2048 + buf*16384
//       B tile (single buffered):  2048 + 32768
//       LN row partials (post-mainloop, reuse tile area): 2048 sSum[128][2], 3072 sSq[128][2]
#define SMEM_DYN (2048 + 2 * 16384 + 16384)   // 51200 -> 2 CTAs/SM

__global__ void __launch_bounds__(256, 2) k_gemm(int layer, const float* __restrict__ bias,
                                                 const float* __restrict__ gamma,
                                                 const float* __restrict__ beta,
                                                 const float* __restrict__ xin,
                                                 float* __restrict__ xout,
                                                 int write_next) {
    extern __shared__ char smem[];
    float* sBias  = (float*)smem;
    float* sGamma = (float*)(smem + 512);
    float* sBeta  = (float*)(smem + 1024);
    uint32_t smem_u = smem_to_u32(smem);
    int tid = threadIdx.x;
    int wid = tid >> 5;
    int lane = tid & 31;
    int brow = blockIdx.x * 128;

    if (tid < 32) {
        *reinterpret_cast<float4*>(&sBias[tid * 4]) =
            *reinterpret_cast<const float4*>(bias + tid * 4);
        *reinterpret_cast<float4*>(&sGamma[tid * 4]) =
            *reinterpret_cast<const float4*>(gamma + tid * 4);
        *reinterpret_cast<float4*>(&sBeta[tid * 4]) =
            *reinterpret_cast<const float4*>(beta + tid * 4);
    }

    const __half* bh = g_bh + (size_t)layer * D * KTOT;

    // warp tile: 32 (m) x 64 (n)
    int wm = wid & 3;            // m0 = wm*32
    int wn = wid >> 2;           // n0 = wn*64
    int lrow = lane & 15;
    int kh16 = (lane >> 4) * 16;

    const uint32_t bBase = smem_u + 2048 + 32768;

    float acc[2][8][4];
#pragma unroll
    for (int t = 0; t < 2; t++)
#pragma unroll
        for (int q = 0; q < 8; q++)
#pragma unroll
            for (int j = 0; j < 4; j++) acc[t][q][j] = 0.f;

    auto load_A = [&](int c, int buf) {
        uint32_t base = smem_u + 2048 + buf * 16384;
        int kcol = c * 64;
#pragma unroll
        for (int it = 0; it < 4; it++) {
            int u = tid + it * 256;          // 0..1023
            int row = u >> 3;                // 0..127
            int c16 = u & 7;
            uint32_t off = row * 128 + c16 * 16;
            uint32_t sw = off ^ ((off >> 3) & 0x70);
            CP16(base + sw, &g_ah[(size_t)(brow + row) * KTOT + kcol + c16 * 8]);
        }
        asm volatile("cp.async.commit_group;" ::: "memory");
    };
    auto load_B = [&](int c) {
        int kcol = c * 64;
#pragma unroll
        for (int it = 0; it < 4; it++) {
            int u = tid + it * 256;          // 0..1023 -> full 128 rows
            int row = u >> 3;
            int c16 = u & 7;
            uint32_t off = row * 128 + c16 * 16;
            uint32_t sw = off ^ ((off >> 3) & 0x70);
            CP16(bBase + sw, &bh[(size_t)row * KTOT + kcol + c16 * 8]);
        }
        asm volatile("cp.async.commit_group;" ::: "memory");
    };

    load_A(0, 0);
    load_B(0);

    for (int c = 0; c < NCHUNK; c++) {
        asm volatile("cp.async.wait_group 0;" ::: "memory");
        __syncthreads();
        if (c + 1 < NCHUNK) load_A(c + 1, (c + 1) & 1);   // A buffer (c+1)&1 is free

        uint32_t base = smem_u + 2048 + (c & 1) * 16384;
#pragma unroll
        for (int ks = 0; ks < 4; ks++) {
            int kb = ks * 32 + kh16;
            uint32_t ah[2][4], bhf[4][4];
#pragma unroll
            for (int t = 0; t < 2; t++) {
                int row = wm * 32 + t * 16 + lrow;
                uint32_t off = row * 128 + kb;
                ldsm_x4(ah[t], base + (off ^ ((off >> 3) & 0x70)));
            }
#pragma unroll
            for (int p = 0; p < 4; p++) {
                int row = wn * 64 + p * 16 + lrow;
                uint32_t off = row * 128 + kb;
                ldsm_x4(bhf[p], bBase + (off ^ ((off >> 3) & 0x70)));
            }
#pragma unroll
            for (int t = 0; t < 2; t++)
#pragma unroll
                for (int p = 0; p < 4; p++) {
                    mma16816(acc[t][2 * p + 0], ah[t], bhf[p][0], bhf[p][2]);
                    mma16816(acc[t][2 * p + 1], ah[t], bhf[p][1], bhf[p][3]);
                }
        }
        __syncthreads();                         // all warps done with B(c)
        if (c + 1 < NCHUNK) load_B(c + 1);       // refill single B buffer
    }
    // after final __syncthreads above, tile smem is dead -> reuse for LN partials

    float* sSum = (float*)(smem + 2048);   // [128][2]
    float* sSq  = (float*)(smem + 3072);   // [128][2]

    // ---- step 1: v = relu(acc + bias) + xin ; accumulate per-row partials ----
    float psum[2][2], psq[2][2];
#pragma unroll
    for (int t = 0; t < 2; t++) {
        int r0 = brow + wm * 32 + t * 16 + (lane >> 2);
        int r1 = r0 + 8;
        float s0 = 0.f, s1 = 0.f, q0 = 0.f, q1 = 0.f;
#pragma unroll
        for (int q = 0; q < 8; q++) {
            int col = wn * 64 + (q >> 1) * 16 + (q & 1) * 8 + 2 * (lane & 3);
            float bx = sBias[col], by = sBias[col + 1];
            float2 x0 = (r0 < N_NODES)
                ? *reinterpret_cast<const float2*>(xin + (size_t)r0 * D + col)
                : make_float2(0.f, 0.f);
            float2 x1 = (r1 < N_NODES)
                ? *reinterpret_cast<const float2*>(xin + (size_t)r1 * D + col)
                : make_float2(0.f, 0.f);
            float v0 = fmaxf(acc[t][q][0] + bx, 0.f) + x0.x;
            float v1 = fmaxf(acc[t][q][1] + by, 0.f) + x0.y;
            float v2 = fmaxf(acc[t][q][2] + bx, 0.f) + x1.x;
            float v3 = fmaxf(acc[t][q][3] + by, 0.f) + x1.y;
            acc[t][q][0] = v0; acc[t][q][1] = v1;
            acc[t][q][2] = v2; acc[t][q][3] = v3;
            s0 += v0 + v1;  q0 += v0 * v0 + v1 * v1;
            s1 += v2 + v3;  q1 += v2 * v2 + v3 * v3;
        }
        psum[t][0] = s0; psum[t][1] = s1;
        psq[t][0] = q0;  psq[t][1] = q1;
    }
    // quad reduce (4 threads share each row)
#pragma unroll
    for (int t = 0; t < 2; t++)
#pragma unroll
        for (int h = 0; h < 2; h++) {
            psum[t][h] += __shfl_xor_sync(0xFFFFFFFFu, psum[t][h], 1);
            psum[t][h] += __shfl_xor_sync(0xFFFFFFFFu, psum[t][h], 2);
            psq[t][h]  += __shfl_xor_sync(0xFFFFFFFFu, psq[t][h], 1);
            psq[t][h]  += __shfl_xor_sync(0xFFFFFFFFu, psq[t][h], 2);
        }
    if ((lane & 3) == 0) {
#pragma unroll
        for (int t = 0; t < 2; t++) {
            int m0 = wm * 32 + t * 16 + (lane >> 2);
            sSum[m0 * 2 + wn] = psum[t][0];
            sSum[(m0 + 8) * 2 + wn] = psum[t][1];
            sSq[m0 * 2 + wn] = psq[t][0];
            sSq[(m0 + 8) * 2 + wn] = psq[t][1];
        }
    }
    __syncthreads();

    // ---- step 2: LN + write xout (+ fp16 self-cols for next layer) ----
#pragma unroll
    for (int t = 0; t < 2; t++) {
        int m0 = wm * 32 + t * 16 + (lane >> 2);
#pragma unroll
        for (int h = 0; h < 2; h++) {
            int m = m0 + h * 8;
            int row = brow + m;
            if (row >= N_NODES) continue;
            float s = sSum[m * 2 + 0] + sSum[m * 2 + 1];
            float sq = sSq[m * 2 + 0] + sSq[m * 2 + 1];
            float mean = s * (1.0f / 128.0f);
            float var = sq * (1.0f / 128.0f) - mean * mean;
            float rs = rsqrtf(var + 1e-5f);
#pragma unroll
            for (int q = 0; q < 8; q++) {
                int col = wn * 64 + (q >> 1) * 16 + (q & 1) * 8 + 2 * (lane & 3);
                float o0 = (acc[t][q][2 * h + 0] - mean) * rs * sGamma[col] + sBeta[col];
                float o1 = (acc[t][q][2 * h + 1] - mean) * rs * sGamma[col + 1] + sBeta[col + 1];
                *reinterpret_cast<float2*>(xout + (size_t)row * D + col) =
                    make_float2(o0, o1);
                if (write_next) {
                    __half2 hp = __floats2half2_rn(o0, o1);
                    *reinterpret_cast<__half2*>(
                        &g_ah[(size_t)row * KTOT + 512 + col]) = hp;
                }
            }
        }
    }
}

// ---------------- host launcher ----------------
extern "C" void kernel_launch(void* const* d_in, const int* in_sizes, int n_in,
                              void* d_out, int out_size) {
    const float* x     = (const float*)d_in[0];
    const int*   ei    = (const int*)d_in[1];
    const int*   et    = (const int*)d_in[2];
    const float* W     = (const float*)d_in[3];
    const float* root  = (const float*)d_in[4];
    const float* bias  = (const float*)d_in[5];
    const float* gamma = (const float*)d_in[6];
    const float* beta  = (const float*)d_in[7];
    float* out = (float*)d_out;

    const int* src = ei;
    const int* dst = ei + N_EDGES;

    float *px1 = nullptr, *px2 = nullptr;
    cudaGetSymbolAddress((void**)&px1, g_x1);
    cudaGetSymbolAddress((void**)&px2, g_x2);

    cudaFuncSetAttribute(k_gemm, cudaFuncAttributeMaxDynamicSharedMemorySize, SMEM_DYN);

    // CSR build (edge structure is layer-invariant)
    k_zero_cnt<<<(NSEG + 255) / 256, 256>>>();
    k_hist<<<(N_EDGES + 255) / 256, 256>>>(dst, et);
    int nb = (NSEG + 1023) / 1024;
    k_scan1<<<nb, 1024>>>();
    k_scan23<<<nb, 1024>>>(nb);
    k_scatter<<<(N_EDGES + 255) / 256, 256>>>(src, dst, et);

    // weight transpose + fp16
    k_bprep<<<(NLAYER * D * KTOT + 255) / 256, 256>>>(W, root);
    // self-cols for layer 0 (must precede first k_agg — it gathers from them)
    k_convx<<<(N_NODES + 7) / 8, 256>>>(x);

    const float* xin = x;
    for (int l = 0; l < NLAYER; l++) {
        k_agg<<<(NSEG + 7) / 8, 256>>>();
        float* xout = (l == NLAYER - 1) ? out : ((l == 0) ? px1 : px2);
        k_gemm<<<NTILES, 256, SMEM_DYN>>>(l, bias + (size_t)l * D,
                                          gamma + (size_t)l * D,
                                          beta + (size_t)l * D,
                                          xin, xout,
                                          l < NLAYER - 1 ? 1 : 0);
        xin = xout;
    }
}

// round 14
// speedup vs baseline: 1.0316x; 1.0316x over previous
#include <cuda_runtime.h>
#include <cuda_fp16.h>
#include <cstdint>

#define N_NODES 50000
#define N_EDGES 800000
#define D 128
#define R 4
#define NSEG (N_NODES * R)      // 200000
#define NLAYER 3
#define KTOT 640                // R*D + D
#define MPAD 50048              // 782 * 64
#define NTILES 782              // M=64 tiles
#define NCHUNK 10               // K chunks of 64 fp16 (128B rows)

// ---------------- static device scratch ----------------
__device__ __align__(16) __half g_ah[(size_t)MPAD * KTOT];        // A fp16 [node][640]
__device__ __align__(16) __half g_bh[(size_t)NLAYER * D * KTOT];  // B fp16 [l][n][k]
__device__ float g_x1[(size_t)N_NODES * D];
__device__ float g_x2[(size_t)N_NODES * D];
__device__ int   g_cnt[NSEG];
__device__ int   g_off[NSEG + 1];
__device__ int   g_cursor[NSEG];
__device__ int   g_bsum[256];
__device__ int   g_srcs[N_EDGES];

// ---------------- helpers ----------------
__device__ __forceinline__ uint32_t smem_to_u32(const void* p) {
    uint32_t a;
    asm("{ .reg .u64 t; cvta.to.shared.u64 t, %1; cvt.u32.u64 %0, t; }"
        : "=r"(a) : "l"(p));
    return a;
}

#define CP16(sm, gp) \
    asm volatile("cp.async.cg.shared.global [%0], [%1], 16;" :: "r"(sm), "l"(gp))

__device__ __forceinline__ void ldsm_x4(uint32_t* f, uint32_t addr) {
    asm volatile("ldmatrix.sync.aligned.m8n8.x4.shared.b16 {%0,%1,%2,%3}, [%4];"
                 : "=r"(f[0]), "=r"(f[1]), "=r"(f[2]), "=r"(f[3]) : "r"(addr));
}

__device__ __forceinline__ void mma16816(float* d, const uint32_t* a,
                                         uint32_t b0, uint32_t b1) {
    asm volatile(
        "mma.sync.aligned.m16n8k16.row.col.f32.f16.f16.f32 "
        "{%0,%1,%2,%3}, {%4,%5,%6,%7}, {%8,%9}, {%0,%1,%2,%3};"
        : "+f"(d[0]), "+f"(d[1]), "+f"(d[2]), "+f"(d[3])
        : "r"(a[0]), "r"(a[1]), "r"(a[2]), "r"(a[3]), "r"(b0), "r"(b1));
}

// ---------------- CSR build ----------------
__global__ void k_zero_cnt() {
    int i = blockIdx.x * blockDim.x + threadIdx.x;
    if (i < NSEG) g_cnt[i] = 0;
}

__global__ void k_hist(const int* __restrict__ dst, const int* __restrict__ et) {
    int e = blockIdx.x * blockDim.x + threadIdx.x;
    if (e < N_EDGES) atomicAdd(&g_cnt[dst[e] * R + et[e]], 1);
}

__global__ void k_scan1() {
    __shared__ int sh[1024];
    int t = threadIdx.x;
    int i = blockIdx.x * 1024 + t;
    int v = (i < NSEG) ? g_cnt[i] : 0;
    sh[t] = v;
    __syncthreads();
    for (int d = 1; d < 1024; d <<= 1) {
        int add = (t >= d) ? sh[t - d] : 0;
        __syncthreads();
        sh[t] += add;
        __syncthreads();
    }
    if (i < NSEG) g_off[i] = sh[t] - v;
    if (t == 1023) g_bsum[blockIdx.x] = sh[1023];
}

// fused scan2+scan3: every block redundantly scans the block sums
__global__ void k_scan23(int nb) {
    __shared__ int sh[256];
    int t = threadIdx.x;
    if (t < 256) sh[t] = (t < nb) ? g_bsum[t] : 0;
    __syncthreads();
    for (int d = 1; d < 256; d <<= 1) {
        int add = 0;
        if (t < 256 && t >= d) add = sh[t - d];
        __syncthreads();
        if (t < 256) sh[t] += add;
        __syncthreads();
    }
    int boff = (blockIdx.x > 0) ? sh[blockIdx.x - 1] : 0;
    int i = blockIdx.x * 1024 + t;
    if (i < NSEG) {
        int o = g_off[i] + boff;
        g_off[i] = o;
        g_cursor[i] = o;
    }
    if (i == 0) g_off[NSEG] = N_EDGES;
}

__global__ void k_scatter(const int* __restrict__ src, const int* __restrict__ dst,
                          const int* __restrict__ et) {
    int e = blockIdx.x * blockDim.x + threadIdx.x;
    if (e < N_EDGES) {
        int seg = dst[e] * R + et[e];
        int pos = atomicAdd(&g_cursor[seg], 1);
        g_srcs[pos] = src[e];
    }
}

// ---------------- weight prep: transpose + fp16 ----------------
__global__ void k_bprep(const float* __restrict__ W, const float* __restrict__ root) {
    int i = blockIdx.x * 256 + threadIdx.x;     // over NLAYER*D*KTOT
    if (i >= NLAYER * D * KTOT) return;
    int k = i % KTOT;
    int t = i / KTOT;
    int n = t % D;
    int l = t / D;
    float w;
    if (k < 512) {
        int r = k >> 7, din = k & 127;
        w = W[(((size_t)l * R + r) * D + din) * D + n];
    } else {
        w = root[((size_t)l * D + (k - 512)) * D + n];
    }
    g_bh[i] = __float2half_rn(w);
}

// ---------------- fill self-columns (512..639) of A from fp32 activations ----------------
__global__ void k_convx(const float* __restrict__ x) {
    int row = blockIdx.x * 8 + (threadIdx.x >> 5);
    if (row >= N_NODES) return;
    int lane = threadIdx.x & 31;
    float4 v = *reinterpret_cast<const float4*>(x + (size_t)row * D + lane * 4);
    __half h[4];
    h[0] = __float2half_rn(v.x);
    h[1] = __float2half_rn(v.y);
    h[2] = __float2half_rn(v.z);
    h[3] = __float2half_rn(v.w);
    size_t o = (size_t)row * KTOT + 512 + lane * 4;
    *reinterpret_cast<uint2*>(&g_ah[o]) = *reinterpret_cast<uint2*>(h);
}

// ---------------- segment-mean aggregation (warp per segment, simple loop) ----------------
__global__ void k_agg() {
    int seg = blockIdx.x * 8 + (threadIdx.x >> 5);
    if (seg >= NSEG) return;
    int lane = threadIdx.x & 31;
    int beg = g_off[seg];
    int end = g_off[seg + 1];
    float ax = 0.f, ay = 0.f, az = 0.f, aw = 0.f;
    for (int j = beg; j < end; j++) {
        int sn = g_srcs[j];
        uint2 raw = *reinterpret_cast<const uint2*>(
            &g_ah[(size_t)sn * KTOT + 512 + lane * 4]);
        __half2 h01 = *reinterpret_cast<__half2*>(&raw.x);
        __half2 h23 = *reinterpret_cast<__half2*>(&raw.y);
        float2 f01 = __half22float2(h01);
        float2 f23 = __half22float2(h23);
        ax += f01.x; ay += f01.y; az += f23.x; aw += f23.y;
    }
    float inv = (end > beg) ? 1.0f / (float)(end - beg) : 0.0f;
    __half h[4];
    h[0] = __float2half_rn(ax * inv);
    h[1] = __float2half_rn(ay * inv);
    h[2] = __float2half_rn(az * inv);
    h[3] = __float2half_rn(aw * inv);
    int node = seg >> 2;
    int r = seg & 3;
    size_t o = (size_t)node * KTOT + r * 128 + lane * 4;
    *reinterpret_cast<uint2*>(&g_ah[o]) = *reinterpret_cast<uint2*>(h);
}

// ---------------- HMMA GEMM (M=64 tiles, occ 3) + fused relu/residual/LayerNorm ----------------
// smem: [0:512) bias, [512:1024) gamma, [1024:1536) beta
//       A tiles (double buffered): 2048 + buf*8192   (64 rows x 128B)
//       B tile (single buffered):  2048 + 16384      (128 rows x 128B)
//       LN partials (post-mainloop, reuse A area): sSum[64][2]@2048, sSq[64][2]@2560
#define SMEM_DYN (2048 + 2 * 8192 + 16384)   // 34816 -> 3 CTAs/SM

__global__ void __launch_bounds__(256, 3) k_gemm(int layer, const float* __restrict__ bias,
                                                 const float* __restrict__ gamma,
                                                 const float* __restrict__ beta,
                                                 const float* __restrict__ xin,
                                                 float* __restrict__ xout,
                                                 int write_next) {
    extern __shared__ char smem[];
    float* sBias  = (float*)smem;
    float* sGamma = (float*)(smem + 512);
    float* sBeta  = (float*)(smem + 1024);
    uint32_t smem_u = smem_to_u32(smem);
    int tid = threadIdx.x;
    int wid = tid >> 5;
    int lane = tid & 31;
    int brow = blockIdx.x * 64;

    if (tid < 32) {
        *reinterpret_cast<float4*>(&sBias[tid * 4]) =
            *reinterpret_cast<const float4*>(bias + tid * 4);
        *reinterpret_cast<float4*>(&sGamma[tid * 4]) =
            *reinterpret_cast<const float4*>(gamma + tid * 4);
        *reinterpret_cast<float4*>(&sBeta[tid * 4]) =
            *reinterpret_cast<const float4*>(beta + tid * 4);
    }

    const __half* bh = g_bh + (size_t)layer * D * KTOT;

    // warp tile: 16 (m) x 64 (n); 4 m-tiles x 2 n-tiles = 8 warps
    int wm = wid & 3;            // m0 = wm*16
    int wn = wid >> 2;           // n0 = wn*64
    int lrow = lane & 15;
    int kh16 = (lane >> 4) * 16;

    const uint32_t bBase = smem_u + 2048 + 16384;

    float acc[8][4];
#pragma unroll
    for (int q = 0; q < 8; q++)
#pragma unroll
        for (int j = 0; j < 4; j++) acc[q][j] = 0.f;

    auto load_A = [&](int c, int buf) {
        uint32_t base = smem_u + 2048 + buf * 8192;
        int kcol = c * 64;
#pragma unroll
        for (int it = 0; it < 2; it++) {
            int u = tid + it * 256;          // 0..511
            int row = u >> 3;                // 0..63
            int c16 = u & 7;
            uint32_t off = row * 128 + c16 * 16;
            uint32_t sw = off ^ ((off >> 3) & 0x70);
            CP16(base + sw, &g_ah[(size_t)(brow + row) * KTOT + kcol + c16 * 8]);
        }
        asm volatile("cp.async.commit_group;" ::: "memory");
    };
    auto load_B = [&](int c) {
        int kcol = c * 64;
#pragma unroll
        for (int it = 0; it < 4; it++) {
            int u = tid + it * 256;          // 0..1023 -> full 128 rows
            int row = u >> 3;
            int c16 = u & 7;
            uint32_t off = row * 128 + c16 * 16;
            uint32_t sw = off ^ ((off >> 3) & 0x70);
            CP16(bBase + sw, &bh[(size_t)row * KTOT + kcol + c16 * 8]);
        }
        asm volatile("cp.async.commit_group;" ::: "memory");
    };

    load_A(0, 0);
    load_B(0);

    for (int c = 0; c < NCHUNK; c++) {
        asm volatile("cp.async.wait_group 0;" ::: "memory");
        __syncthreads();
        if (c + 1 < NCHUNK) load_A(c + 1, (c + 1) & 1);   // A buffer (c+1)&1 is free

        uint32_t base = smem_u + 2048 + (c & 1) * 8192;
#pragma unroll
        for (int ks = 0; ks < 4; ks++) {
            int kb = ks * 32 + kh16;
            uint32_t ah[4], bhf[4][4];
            {
                int row = wm * 16 + lrow;
                uint32_t off = row * 128 + kb;
                ldsm_x4(ah, base + (off ^ ((off >> 3) & 0x70)));
            }
#pragma unroll
            for (int p = 0; p < 4; p++) {
                int row = wn * 64 + p * 16 + lrow;
                uint32_t off = row * 128 + kb;
                ldsm_x4(bhf[p], bBase + (off ^ ((off >> 3) & 0x70)));
            }
#pragma unroll
            for (int p = 0; p < 4; p++) {
                mma16816(acc[2 * p + 0], ah, bhf[p][0], bhf[p][2]);
                mma16816(acc[2 * p + 1], ah, bhf[p][1], bhf[p][3]);
            }
        }
        __syncthreads();                         // all warps done with B(c)
        if (c + 1 < NCHUNK) load_B(c + 1);       // refill single B buffer
    }
    // tile smem dead after final sync -> reuse for LN partials

    float* sSum = (float*)(smem + 2048);   // [64][2]
    float* sSq  = (float*)(smem + 2560);   // [64][2]

    // ---- step 1: v = relu(acc + bias) + xin ; per-row partials ----
    int r0 = brow + wm * 16 + (lane >> 2);
    int r1 = r0 + 8;
    float s0 = 0.f, s1 = 0.f, q0 = 0.f, q1 = 0.f;
#pragma unroll
    for (int q = 0; q < 8; q++) {
        int col = wn * 64 + (q >> 1) * 16 + (q & 1) * 8 + 2 * (lane & 3);
        float bx = sBias[col], by = sBias[col + 1];
        float2 x0 = (r0 < N_NODES)
            ? *reinterpret_cast<const float2*>(xin + (size_t)r0 * D + col)
            : make_float2(0.f, 0.f);
        float2 x1 = (r1 < N_NODES)
            ? *reinterpret_cast<const float2*>(xin + (size_t)r1 * D + col)
            : make_float2(0.f, 0.f);
        float v0 = fmaxf(acc[q][0] + bx, 0.f) + x0.x;
        float v1 = fmaxf(acc[q][1] + by, 0.f) + x0.y;
        float v2 = fmaxf(acc[q][2] + bx, 0.f) + x1.x;
        float v3 = fmaxf(acc[q][3] + by, 0.f) + x1.y;
        acc[q][0] = v0; acc[q][1] = v1;
        acc[q][2] = v2; acc[q][3] = v3;
        s0 += v0 + v1;  q0 += v0 * v0 + v1 * v1;
        s1 += v2 + v3;  q1 += v2 * v2 + v3 * v3;
    }
    // quad reduce (4 threads share each row)
    s0 += __shfl_xor_sync(0xFFFFFFFFu, s0, 1);
    s0 += __shfl_xor_sync(0xFFFFFFFFu, s0, 2);
    s1 += __shfl_xor_sync(0xFFFFFFFFu, s1, 1);
    s1 += __shfl_xor_sync(0xFFFFFFFFu, s1, 2);
    q0 += __shfl_xor_sync(0xFFFFFFFFu, q0, 1);
    q0 += __shfl_xor_sync(0xFFFFFFFFu, q0, 2);
    q1 += __shfl_xor_sync(0xFFFFFFFFu, q1, 1);
    q1 += __shfl_xor_sync(0xFFFFFFFFu, q1, 2);
    if ((lane & 3) == 0) {
        int m0 = wm * 16 + (lane >> 2);
        sSum[m0 * 2 + wn] = s0;
        sSum[(m0 + 8) * 2 + wn] = s1;
        sSq[m0 * 2 + wn] = q0;
        sSq[(m0 + 8) * 2 + wn] = q1;
    }
    __syncthreads();

    // ---- step 2: LN + write xout (+ fp16 self-cols for next layer) ----
    int m0 = wm * 16 + (lane >> 2);
#pragma unroll
    for (int h = 0; h < 2; h++) {
        int m = m0 + h * 8;
        int row = brow + m;
        if (row >= N_NODES) continue;
        float s = sSum[m * 2 + 0] + sSum[m * 2 + 1];
        float sq = sSq[m * 2 + 0] + sSq[m * 2 + 1];
        float mean = s * (1.0f / 128.0f);
        float var = sq * (1.0f / 128.0f) - mean * mean;
        float rs = rsqrtf(var + 1e-5f);
#pragma unroll
        for (int q = 0; q < 8; q++) {
            int col = wn * 64 + (q >> 1) * 16 + (q & 1) * 8 + 2 * (lane & 3);
            float o0 = (acc[q][2 * h + 0] - mean) * rs * sGamma[col] + sBeta[col];
            float o1 = (acc[q][2 * h + 1] - mean) * rs * sGamma[col + 1] + sBeta[col + 1];
            *reinterpret_cast<float2*>(xout + (size_t)row * D + col) =
                make_float2(o0, o1);
            if (write_next) {
                __half2 hp = __floats2half2_rn(o0, o1);
                *reinterpret_cast<__half2*>(
                    &g_ah[(size_t)row * KTOT + 512 + col]) = hp;
            }
        }
    }
}

// ---------------- host launcher ----------------
extern "C" void kernel_launch(void* const* d_in, const int* in_sizes, int n_in,
                              void* d_out, int out_size) {
    const float* x     = (const float*)d_in[0];
    const int*   ei    = (const int*)d_in[1];
    const int*   et    = (const int*)d_in[2];
    const float* W     = (const float*)d_in[3];
    const float* root  = (const float*)d_in[4];
    const float* bias  = (const float*)d_in[5];
    const float* gamma = (const float*)d_in[6];
    const float* beta  = (const float*)d_in[7];
    float* out = (float*)d_out;

    const int* src = ei;
    const int* dst = ei + N_EDGES;

    float *px1 = nullptr, *px2 = nullptr;
    cudaGetSymbolAddress((void**)&px1, g_x1);
    cudaGetSymbolAddress((void**)&px2, g_x2);

    cudaFuncSetAttribute(k_gemm, cudaFuncAttributeMaxDynamicSharedMemorySize, SMEM_DYN);

    // CSR build (edge structure is layer-invariant)
    k_zero_cnt<<<(NSEG + 255) / 256, 256>>>();
    k_hist<<<(N_EDGES + 255) / 256, 256>>>(dst, et);
    int nb = (NSEG + 1023) / 1024;
    k_scan1<<<nb, 1024>>>();
    k_scan23<<<nb, 1024>>>(nb);
    k_scatter<<<(N_EDGES + 255) / 256, 256>>>(src, dst, et);

    // weight transpose + fp16
    k_bprep<<<(NLAYER * D * KTOT + 255) / 256, 256>>>(W, root);
    // self-cols for layer 0 (must precede first k_agg — it gathers from them)
    k_convx<<<(N_NODES + 7) / 8, 256>>>(x);

    const float* xin = x;
    for (int l = 0; l < NLAYER; l++) {
        k_agg<<<(NSEG + 7) / 8, 256>>>();
        float* xout = (l == NLAYER - 1) ? out : ((l == 0) ? px1 : px2);
        k_gemm<<<NTILES, 256, SMEM_DYN>>>(l, bias + (size_t)l * D,
                                          gamma + (size_t)l * D,
                                          beta + (size_t)l * D,
                                          xin, xout,
                                          l < NLAYER - 1 ? 1 : 0);
        xin = xout;
    }
}